// round 12
// baseline (speedup 1.0000x reference)
#include <cuda_runtime.h>
#include <cuda_bf16.h>
#include <stdint.h>

// PyramidROIAlign: output [B,N,7,7,256] f32, levels p2..p5 (256/128/64/32), NHWC.
// R12: spatial-binning pipeline to break the LTS (L2 bandwidth) wall.
//  The 392MB gather flow has ~2-25x spatial reuse across overlapping ROIs, but
//  it is only captured in L2 (samples scatter across SMs). We sort samples by
//  spatial bin (b,lvl,y0>>3,x0>>3) and let each CTA process 64 consecutive
//  bin-sorted samples -> the bin's pixel rows stay resident in that SM's L1.
//  K0 zero hist -> K1 records+bins+hist -> K2 scan -> K3 scatter -> K4 main.

#define POOLX 7
#define MAX_ROIS 8192
#define MAXS (MAX_ROIS * 49)
#define NBINS 8192

__device__ float4 g_recs[MAXS];
__device__ int    g_bin[MAXS];
__device__ int    g_sorted[MAXS];
__device__ int    g_hist[NBINS];
__device__ int    g_cursor[NBINS];

__global__ void zero_hist_kernel() {
    int t = blockIdx.x * blockDim.x + threadIdx.x;
    if (t < NBINS) g_hist[t] = 0;
}

__global__ __launch_bounds__(256) void roi_setup_kernel(
    const float* __restrict__ boxes,   // [M,4]
    const float* __restrict__ meta,    // [B,93]
    int total, int N)
{
    int tid = blockIdx.x * blockDim.x + threadIdx.x;
    if (tid >= total) return;
    int pos = tid % 49;
    int roi = tid / 49;
    int b   = roi / N;
    int py  = pos / POOLX;
    int px  = pos - py * POOLX;

    float4 bx = __ldg(((const float4*)boxes) + roi);
    float y1 = bx.x, x1 = bx.y, y2 = bx.z, x2 = bx.w;
    float h = y2 - y1, w = x2 - x1;

    float area  = __ldg(meta + 4) * __ldg(meta + 5);
    float scale = sqrtf(fmaxf(h * w, 1e-12f));
    float rl    = log2f(scale * sqrtf(area) / 224.0f);
    int lvl = 4 + (int)rintf(rl);
    lvl = min(max(lvl, 2), 5);

    int H = 256 >> (lvl - 2);          // 256,128,64,32
    int W = H;

    float ty = (float)py * (1.0f / 6.0f);
    float tx = (float)px * (1.0f / 6.0f);
    float ys = (y1 + ty * h) * (float)(H - 1);
    float xs = (x1 + tx * w) * (float)(W - 1);

    float fy = floorf(ys), fx = floorf(xs);
    float ly = ys - fy,    lx = xs - fx;

    int y0  = min(max((int)fy,     0), H - 1);
    int y1i = min(max((int)fy + 1, 0), H - 1);
    int x0  = min(max((int)fx,     0), W - 1);
    int x1i = min(max((int)fx + 1, 0), W - 1);

    uint32_t off00 = (uint32_t)(((b * H + y0 ) * W + x0) * 64);  // float4 units
    uint32_t off10 = (uint32_t)(((b * H + y1i) * W + x0) * 64);
    uint32_t dx    = (uint32_t)(x1i - x0);                       // 0 or 1

    float4 rec;
    rec.x = __uint_as_float(off00 | (dx << 23) | ((uint32_t)(lvl - 2) << 24));
    rec.y = __uint_as_float(off10);
    rec.z = lx;
    rec.w = ly;
    g_recs[tid] = rec;

    // Spatial bin: 8x8 pixel tiles at the sample's level.
    // Levels have <=32x32 tiles; key fits in 8192 bins.
    int bin = (((b * 4 + (lvl - 2)) * 32 + (y0 >> 3)) & 0xFF) * 32 + ((x0 >> 3) & 31);
    bin &= (NBINS - 1);
    g_bin[tid] = bin;
    atomicAdd(&g_hist[bin], 1);
}

// Exclusive scan of g_hist[8192] -> g_cursor[8192]. One block, 1024 threads x 8.
__global__ __launch_bounds__(1024) void scan_kernel() {
    __shared__ int part[1024];
    int t = threadIdx.x;
    int base = t * 8;
    int loc[8];
    int s = 0;
    #pragma unroll
    for (int i = 0; i < 8; i++) { loc[i] = s; s += g_hist[base + i]; }
    part[t] = s;
    __syncthreads();
    // Kogge-Stone inclusive scan on part[]
    #pragma unroll
    for (int off = 1; off < 1024; off <<= 1) {
        int v = (t >= off) ? part[t - off] : 0;
        __syncthreads();
        part[t] += v;
        __syncthreads();
    }
    int prefix = part[t] - s;   // exclusive prefix of this thread's chunk
    #pragma unroll
    for (int i = 0; i < 8; i++) g_cursor[base + i] = prefix + loc[i];
}

__global__ __launch_bounds__(256) void scatter_kernel(int total) {
    int tid = blockIdx.x * blockDim.x + threadIdx.x;
    if (tid >= total) return;
    int bin = g_bin[tid];
    int pos = atomicAdd(&g_cursor[bin], 1);
    g_sorted[pos] = tid;
}

// Main: each CTA processes 64 consecutive bin-sorted samples (8 warps x 8 iters);
// the bin's feature-map rows stay L1-resident across iterations.
__global__ __launch_bounds__(256, 6) void roi_align_main_kernel(
    const float* __restrict__ p2,
    const float* __restrict__ p3,
    const float* __restrict__ p4,
    const float* __restrict__ p5,
    float* __restrict__ out,
    int total)
{
    int w    = threadIdx.x >> 5;
    int lane = threadIdx.x & 31;
    int baseS = blockIdx.x * 64;

    #pragma unroll
    for (int it = 0; it < 8; it++) {
        int s = baseS + it * 8 + w;
        if (s >= total) return;
        int sidx = __ldg(&g_sorted[s]);

        float4 rec = __ldg(&g_recs[sidx]);
        uint32_t a = __float_as_uint(rec.x);
        int o00   = (int)(a & 0x7FFFFFu);
        int dx64  = (int)((a >> 23) & 1u) << 6;
        int lvl   = (int)(a >> 24);
        int o10   = (int)__float_as_uint(rec.y);
        float lx  = rec.z;
        float ly  = rec.w;

        const float* fp = (lvl == 0) ? p2 : (lvl == 1) ? p3 : (lvl == 2) ? p4 : p5;
        const float4* f4 = (const float4*)fp;

        float w11 = ly * lx;
        float w01 = lx - w11;
        float w10 = ly - w11;
        float w00 = 1.0f - lx - w10;

        int cA = lane, cB = lane + 32;
        int o01 = o00 + dx64;
        int o11 = o10 + dx64;

        float4 a00 = __ldg(f4 + o00 + cA);
        float4 a01 = __ldg(f4 + o01 + cA);
        float4 a10 = __ldg(f4 + o10 + cA);
        float4 a11 = __ldg(f4 + o11 + cA);
        float4 b00 = __ldg(f4 + o00 + cB);
        float4 b01 = __ldg(f4 + o01 + cB);
        float4 b10 = __ldg(f4 + o10 + cB);
        float4 b11 = __ldg(f4 + o11 + cB);

        float4 ra, rb;
        ra.x = fmaf(a01.x, w01, a00.x * w00);
        ra.y = fmaf(a01.y, w01, a00.y * w00);
        ra.z = fmaf(a01.z, w01, a00.z * w00);
        ra.w = fmaf(a01.w, w01, a00.w * w00);
        ra.x = fmaf(a10.x, w10, ra.x); ra.x = fmaf(a11.x, w11, ra.x);
        ra.y = fmaf(a10.y, w10, ra.y); ra.y = fmaf(a11.y, w11, ra.y);
        ra.z = fmaf(a10.z, w10, ra.z); ra.z = fmaf(a11.z, w11, ra.z);
        ra.w = fmaf(a10.w, w10, ra.w); ra.w = fmaf(a11.w, w11, ra.w);

        rb.x = fmaf(b01.x, w01, b00.x * w00);
        rb.y = fmaf(b01.y, w01, b00.y * w00);
        rb.z = fmaf(b01.z, w01, b00.z * w00);
        rb.w = fmaf(b01.w, w01, b00.w * w00);
        rb.x = fmaf(b10.x, w10, rb.x); rb.x = fmaf(b11.x, w11, rb.x);
        rb.y = fmaf(b10.y, w10, rb.y); rb.y = fmaf(b11.y, w11, rb.y);
        rb.z = fmaf(b10.z, w10, rb.z); rb.z = fmaf(b11.z, w11, rb.z);
        rb.w = fmaf(b10.w, w10, rb.w); rb.w = fmaf(b11.w, w11, rb.w);

        float4* o4 = (float4*)out + (long)sidx * 64;
        __stcs(o4 + cA, ra);
        __stcs(o4 + cB, rb);
    }
}

extern "C" void kernel_launch(void* const* d_in, const int* in_sizes, int n_in,
                              void* d_out, int out_size) {
    const float* boxes = (const float*)d_in[0];
    const float* meta  = (const float*)d_in[1];
    const float* p2    = (const float*)d_in[2];
    const float* p3    = (const float*)d_in[3];
    const float* p4    = (const float*)d_in[4];
    const float* p5    = (const float*)d_in[5];
    float* out = (float*)d_out;

    int B = in_sizes[1] / 93;              // image_meta [B,93]
    if (B <= 0) B = 2;
    int N = in_sizes[0] / (4 * B);         // boxes [B,N,4]
    int M = B * N;
    if (M > MAX_ROIS) M = MAX_ROIS;
    int total = M * 49;

    zero_hist_kernel<<<(NBINS + 255) / 256, 256>>>();
    roi_setup_kernel<<<(total + 255) / 256, 256>>>(boxes, meta, total, N);
    scan_kernel<<<1, 1024>>>();
    scatter_kernel<<<(total + 255) / 256, 256>>>(total);

    int blocks = (total + 63) / 64;
    roi_align_main_kernel<<<blocks, 256>>>(p2, p3, p4, p5, out, total);
}

// round 13
// speedup vs baseline: 1.5544x; 1.5544x over previous
#include <cuda_runtime.h>
#include <cuda_bf16.h>

// PyramidROIAlign: output [B,N,7,7,256] f32, levels p2..p5 (256/128/64/32), NHWC.
// R13: warp = (roi, py, pxPair) -> handles px = 2p and 2p+1 (p=3: px=6 only).
// ROI-level + y setup computed once per warp (amortized over 2 cells); hot path
// per cell = 8x LDG.128 front-batched + FFMA lerp + 2x STG.128 streaming.
// We are at the L1tex line-service floor (~40 lines/sample @ ~2 cyc/line);
// this round trims residual issue overhead and keeps tail quantization ~1%.

#define POOLX 7
#define C4N 64   // 256 ch / 4

__global__ __launch_bounds__(256, 5) void roi_align_pair_kernel(
    const float* __restrict__ boxes,   // [M,4]  (y1,x1,y2,x2)
    const float* __restrict__ meta,    // [B,93]
    const float* __restrict__ p2,
    const float* __restrict__ p3,
    const float* __restrict__ p4,
    const float* __restrict__ p5,
    float* __restrict__ out,
    int totalWarps, int N)
{
    int gw   = (blockIdx.x * blockDim.x + threadIdx.x) >> 5;  // (roi,py,pxPair)
    int lane = threadIdx.x & 31;
    if (gw >= totalWarps) return;

    int pr  = gw & 3;            // px pair: 0..3  (warpsPerRow = 4, power of 2)
    int t   = gw >> 2;           // roi*7 + py
    int py  = t % POOLX;
    int roi = t / POOLX;
    int b   = roi / N;
    int px0 = pr * 2;
    int nPx = (pr == 3) ? 1 : 2;

    // ---- per-warp setup (shared by both cells) ----
    float4 bx = __ldg(((const float4*)boxes) + roi);
    float y1 = bx.x, x1 = bx.y, y2 = bx.z, x2 = bx.w;
    float h = y2 - y1, w = x2 - x1;

    float area  = __ldg(meta + 4) * __ldg(meta + 5);
    float scale = sqrtf(fmaxf(h * w, 1e-12f));
    float rl    = log2f(scale * sqrtf(area) / 224.0f);
    int lvl = 4 + (int)rintf(rl);
    lvl = min(max(lvl, 2), 5);

    const float* fmap;
    int H;
    if      (lvl == 2) { fmap = p2; H = 256; }
    else if (lvl == 3) { fmap = p3; H = 128; }
    else if (lvl == 4) { fmap = p4; H = 64;  }
    else               { fmap = p5; H = 32;  }
    const int W = H;

    float ty = (float)py * (1.0f / 6.0f);
    float ys = (y1 + ty * h) * (float)(H - 1);
    float fy = floorf(ys);
    float ly = ys - fy;
    int y0  = min(max((int)fy,     0), H - 1);
    int y1i = min(max((int)fy + 1, 0), H - 1);

    int rowT = (b * H + y0 ) * W;
    int rowB = (b * H + y1i) * W;

    float xsc = x1 * (float)(W - 1);
    float xst = w * (float)(W - 1) * (1.0f / 6.0f);

    const float4* f4 = (const float4*)fmap;
    // output float4 base for cell (roi,py,px0)
    float4* obase = (float4*)out + ((long)t * POOLX + px0) * C4N + lane;

    #pragma unroll
    for (int k = 0; k < 2; k++) {
        if (k >= nPx) break;
        int px = px0 + k;

        float xs = fmaf((float)px, xst, xsc);
        float fx = floorf(xs);
        float lx = xs - fx;
        int x0  = min(max((int)fx,     0), W - 1);
        int x1i = min(max((int)fx + 1, 0), W - 1);

        float w11 = ly * lx;
        float w01 = lx - w11;              // lx*(1-ly)
        float w10 = ly - w11;              // ly*(1-lx)
        float w00 = 1.0f - lx - w10;       // (1-lx)*(1-ly)

        int o00 = (rowT + x0 ) * C4N + lane;
        int o01 = (rowT + x1i) * C4N + lane;
        int o10 = (rowB + x0 ) * C4N + lane;
        int o11 = (rowB + x1i) * C4N + lane;

        float4 a00 = __ldg(f4 + o00);
        float4 a01 = __ldg(f4 + o01);
        float4 a10 = __ldg(f4 + o10);
        float4 a11 = __ldg(f4 + o11);
        float4 b00 = __ldg(f4 + o00 + 32);
        float4 b01 = __ldg(f4 + o01 + 32);
        float4 b10 = __ldg(f4 + o10 + 32);
        float4 b11 = __ldg(f4 + o11 + 32);

        float4 ra, rb;
        ra.x = fmaf(a01.x, w01, a00.x * w00);
        ra.y = fmaf(a01.y, w01, a00.y * w00);
        ra.z = fmaf(a01.z, w01, a00.z * w00);
        ra.w = fmaf(a01.w, w01, a00.w * w00);
        ra.x = fmaf(a10.x, w10, ra.x); ra.x = fmaf(a11.x, w11, ra.x);
        ra.y = fmaf(a10.y, w10, ra.y); ra.y = fmaf(a11.y, w11, ra.y);
        ra.z = fmaf(a10.z, w10, ra.z); ra.z = fmaf(a11.z, w11, ra.z);
        ra.w = fmaf(a10.w, w10, ra.w); ra.w = fmaf(a11.w, w11, ra.w);

        rb.x = fmaf(b01.x, w01, b00.x * w00);
        rb.y = fmaf(b01.y, w01, b00.y * w00);
        rb.z = fmaf(b01.z, w01, b00.z * w00);
        rb.w = fmaf(b01.w, w01, b00.w * w00);
        rb.x = fmaf(b10.x, w10, rb.x); rb.x = fmaf(b11.x, w11, rb.x);
        rb.y = fmaf(b10.y, w10, rb.y); rb.y = fmaf(b11.y, w11, rb.y);
        rb.z = fmaf(b10.z, w10, rb.z); rb.z = fmaf(b11.z, w11, rb.z);
        rb.w = fmaf(b10.w, w10, rb.w); rb.w = fmaf(b11.w, w11, rb.w);

        __stcs(obase + k * C4N,      ra);
        __stcs(obase + k * C4N + 32, rb);
    }
}

extern "C" void kernel_launch(void* const* d_in, const int* in_sizes, int n_in,
                              void* d_out, int out_size) {
    const float* boxes = (const float*)d_in[0];
    const float* meta  = (const float*)d_in[1];
    const float* p2    = (const float*)d_in[2];
    const float* p3    = (const float*)d_in[3];
    const float* p4    = (const float*)d_in[4];
    const float* p5    = (const float*)d_in[5];
    float* out = (float*)d_out;

    int B = in_sizes[1] / 93;              // image_meta [B,93]
    if (B <= 0) B = 2;
    int N = in_sizes[0] / (4 * B);         // boxes [B,N,4]
    int M = B * N;
    int totalWarps = M * POOLX * 4;        // warp per (roi, py, pxPair)

    int threads = 256;                      // 8 warps per block
    int warpsPerBlock = threads / 32;
    int blocks = (totalWarps + warpsPerBlock - 1) / warpsPerBlock;
    roi_align_pair_kernel<<<blocks, threads>>>(boxes, meta, p2, p3, p4, p5, out,
                                               totalWarps, N);
}

// round 14
// speedup vs baseline: 1.5855x; 1.0200x over previous
#include <cuda_runtime.h>
#include <cuda_bf16.h>

// PyramidROIAlign: output [B,N,7,7,256] f32, levels p2..p5 (256/128/64/32), NHWC.
// R14: warp = (roi, py, channelHalf). Each warp owns 32 float4 channels
// (cBase = half*32 + lane) and loops over the 7 px cells of the pool row.
//  - ROI/level/y setup computed once per warp, amortized over 7 cells (R4 win)
//  - per cell only 4x LDG.128 + 16 FFMA + 1x STG.128 -> ~40 live regs
//    (fixes R4's 64-reg ILP collapse), 48 warps/SM resident
//  - MLP_p1 = 4 keeps cross-CTA L1tex queue spread low.

#define POOLX 7
#define C4N 64   // 256 ch / 4

__global__ __launch_bounds__(256, 6) void roi_align_half_kernel(
    const float* __restrict__ boxes,   // [M,4]  (y1,x1,y2,x2)
    const float* __restrict__ meta,    // [B,93]
    const float* __restrict__ p2,
    const float* __restrict__ p3,
    const float* __restrict__ p4,
    const float* __restrict__ p5,
    float* __restrict__ out,
    int totalWarps, int N)
{
    int gw   = (blockIdx.x * blockDim.x + threadIdx.x) >> 5;
    int lane = threadIdx.x & 31;
    if (gw >= totalWarps) return;

    int half = gw & 1;           // channel half: 0 -> ch[0..128), 1 -> ch[128..256)
    int t    = gw >> 1;          // roi*7 + py
    int py   = t % POOLX;
    int roi  = t / POOLX;
    int b    = roi / N;
    int cB   = half * 32 + lane; // float4 channel index this thread owns

    // ---- per-warp setup, amortized over 7 cells ----
    float4 bx = __ldg(((const float4*)boxes) + roi);
    float y1 = bx.x, x1 = bx.y, y2 = bx.z, x2 = bx.w;
    float h = y2 - y1, w = x2 - x1;

    float area  = __ldg(meta + 4) * __ldg(meta + 5);
    float scale = sqrtf(fmaxf(h * w, 1e-12f));
    float rl    = log2f(scale * sqrtf(area) / 224.0f);
    int lvl = 4 + (int)rintf(rl);
    lvl = min(max(lvl, 2), 5);

    const float* fmap;
    int H;
    if      (lvl == 2) { fmap = p2; H = 256; }
    else if (lvl == 3) { fmap = p3; H = 128; }
    else if (lvl == 4) { fmap = p4; H = 64;  }
    else               { fmap = p5; H = 32;  }
    const int W = H;

    float ty = (float)py * (1.0f / 6.0f);
    float ys = (y1 + ty * h) * (float)(H - 1);
    float fy = floorf(ys);
    float ly = ys - fy;
    int y0  = min(max((int)fy,     0), H - 1);
    int y1i = min(max((int)fy + 1, 0), H - 1);

    int rowT = (b * H + y0 ) * W;
    int rowB = (b * H + y1i) * W;

    float xsc = x1 * (float)(W - 1);
    float xst = w * (float)(W - 1) * (1.0f / 6.0f);

    const float4* f4 = (const float4*)fmap;
    // output float4 pointer for cell (roi,py,0), this thread's channel
    float4* obase = (float4*)out + (long)t * (POOLX * C4N) + cB;

    #pragma unroll
    for (int px = 0; px < POOLX; px++) {
        float xs = fmaf((float)px, xst, xsc);
        float fx = floorf(xs);
        float lx = xs - fx;
        int x0  = min(max((int)fx,     0), W - 1);
        int x1i = min(max((int)fx + 1, 0), W - 1);

        float w11 = ly * lx;
        float w01 = lx - w11;              // lx*(1-ly)
        float w10 = ly - w11;              // ly*(1-lx)
        float w00 = 1.0f - lx - w10;       // (1-lx)*(1-ly)

        float4 v00 = __ldg(f4 + (rowT + x0 ) * C4N + cB);
        float4 v01 = __ldg(f4 + (rowT + x1i) * C4N + cB);
        float4 v10 = __ldg(f4 + (rowB + x0 ) * C4N + cB);
        float4 v11 = __ldg(f4 + (rowB + x1i) * C4N + cB);

        float4 r;
        r.x = fmaf(v01.x, w01, v00.x * w00);
        r.y = fmaf(v01.y, w01, v00.y * w00);
        r.z = fmaf(v01.z, w01, v00.z * w00);
        r.w = fmaf(v01.w, w01, v00.w * w00);
        r.x = fmaf(v10.x, w10, r.x); r.x = fmaf(v11.x, w11, r.x);
        r.y = fmaf(v10.y, w10, r.y); r.y = fmaf(v11.y, w11, r.y);
        r.z = fmaf(v10.z, w10, r.z); r.z = fmaf(v11.z, w11, r.z);
        r.w = fmaf(v10.w, w10, r.w); r.w = fmaf(v11.w, w11, r.w);

        __stcs(obase + px * C4N, r);
    }
}

extern "C" void kernel_launch(void* const* d_in, const int* in_sizes, int n_in,
                              void* d_out, int out_size) {
    const float* boxes = (const float*)d_in[0];
    const float* meta  = (const float*)d_in[1];
    const float* p2    = (const float*)d_in[2];
    const float* p3    = (const float*)d_in[3];
    const float* p4    = (const float*)d_in[4];
    const float* p5    = (const float*)d_in[5];
    float* out = (float*)d_out;

    int B = in_sizes[1] / 93;              // image_meta [B,93]
    if (B <= 0) B = 2;
    int N = in_sizes[0] / (4 * B);         // boxes [B,N,4]
    int M = B * N;
    int totalWarps = M * POOLX * 2;        // warp per (roi, py, channelHalf)

    int threads = 256;                      // 8 warps per block
    int warpsPerBlock = threads / 32;
    int blocks = (totalWarps + warpsPerBlock - 1) / warpsPerBlock;
    roi_align_half_kernel<<<blocks, threads>>>(boxes, meta, p2, p3, p4, p5, out,
                                               totalWarps, N);
}

// round 15
// speedup vs baseline: 1.6657x; 1.0506x over previous
#include <cuda_runtime.h>
#include <cuda_bf16.h>

// PyramidROIAlign: output [B,N,7,7,256] f32, levels p2..p5 (256/128/64/32), NHWC.
// R15: R3 (best: warp/sample, 8 batched LDG.128, .cs stores, occ 83%) with
// setup issue trimmed:
//  - runtime division b = roi/N replaced by warp-uniform subtract loop (B small)
//  - meta[4]*meta[5] via one LDG.64
//  - log2(scale*sqrt(area)/224) = log2(scale) + 0.5*log2(area) - log2(224)
// Hot path identical to R3 -> same numerics (rel_err 2.5e-6).

#define POOLX 7
#define C4N 64   // 256 ch / 4

__global__ __launch_bounds__(256, 8) void roi_align_warp_kernel(
    const float* __restrict__ boxes,   // [M,4]  (y1,x1,y2,x2)
    const float* __restrict__ meta,    // [B,93]
    const float* __restrict__ p2,
    const float* __restrict__ p3,
    const float* __restrict__ p4,
    const float* __restrict__ p5,
    float* __restrict__ out,
    int totalWarps, int N)
{
    int gw   = (blockIdx.x * blockDim.x + threadIdx.x) >> 5;  // warp id = sample id
    int lane = threadIdx.x & 31;
    if (gw >= totalWarps) return;

    int pos = gw % 49;
    int roi = gw / 49;
    int py  = pos / POOLX;
    int px  = pos - py * POOLX;

    // b = roi / N without runtime IDIV (B is tiny; warp-uniform, <=B iterations)
    int b = 0, r = roi;
    while (r >= N) { r -= N; b++; }

    // ---- per-warp uniform setup ----
    float4 bx = __ldg(((const float4*)boxes) + roi);
    float y1 = bx.x, x1 = bx.y, y2 = bx.z, x2 = bx.w;
    float h = y2 - y1, w = x2 - x1;

    float2 hw = __ldg((const float2*)(meta + 4));   // meta[4], meta[5]
    float area = hw.x * hw.y;

    // log2(scale * sqrt(area) / 224) = 0.5*log2(max(h*w,1e-12)) + 0.5*log2(area) - log2(224)
    float rl = 0.5f * (__log2f(fmaxf(h * w, 1e-12f)) + __log2f(area)) - 7.8073549221f;
    int lvl = 4 + (int)rintf(rl);
    lvl = min(max(lvl, 2), 5);

    const float* fmap;
    int H;
    if      (lvl == 2) { fmap = p2; H = 256; }
    else if (lvl == 3) { fmap = p3; H = 128; }
    else if (lvl == 4) { fmap = p4; H = 64;  }
    else               { fmap = p5; H = 32;  }
    const int W = H;

    float ty = (float)py * (1.0f / 6.0f);
    float tx = (float)px * (1.0f / 6.0f);
    float ys = (y1 + ty * h) * (float)(H - 1);
    float xs = (x1 + tx * w) * (float)(W - 1);

    float fy = floorf(ys), fx = floorf(xs);
    float ly = ys - fy,    lx = xs - fx;

    int y0  = min(max((int)fy,     0), H - 1);
    int y1i = min(max((int)fy + 1, 0), H - 1);
    int x0  = min(max((int)fx,     0), W - 1);
    int x1i = min(max((int)fx + 1, 0), W - 1);

    float w11 = ly * lx;
    float w01 = lx - w11;            // lx*(1-ly)
    float w10 = ly - w11;            // ly*(1-lx)
    float w00 = 1.0f - lx - w10;     // (1-lx)*(1-ly)

    const float4* f4 = (const float4*)fmap;
    int rowT = (b * H + y0 ) * W;
    int rowB = (b * H + y1i) * W;
    int cA = lane, cB = lane + 32;
    int o00 = (rowT + x0 ) * C4N + cA;
    int o01 = (rowT + x1i) * C4N + cA;
    int o10 = (rowB + x0 ) * C4N + cA;
    int o11 = (rowB + x1i) * C4N + cA;

    // ---- hot path: 8x LDG.128 batched, FFMAs, 2x STG.128 .cs ----
    float4 a00 = __ldg(f4 + o00);
    float4 a01 = __ldg(f4 + o01);
    float4 a10 = __ldg(f4 + o10);
    float4 a11 = __ldg(f4 + o11);
    float4 b00 = __ldg(f4 + o00 + 32);
    float4 b01 = __ldg(f4 + o01 + 32);
    float4 b10 = __ldg(f4 + o10 + 32);
    float4 b11 = __ldg(f4 + o11 + 32);

    float4 ra, rb;
    ra.x = a00.x*w00 + a01.x*w01 + a10.x*w10 + a11.x*w11;
    ra.y = a00.y*w00 + a01.y*w01 + a10.y*w10 + a11.y*w11;
    ra.z = a00.z*w00 + a01.z*w01 + a10.z*w10 + a11.z*w11;
    ra.w = a00.w*w00 + a01.w*w01 + a10.w*w10 + a11.w*w11;
    rb.x = b00.x*w00 + b01.x*w01 + b10.x*w10 + b11.x*w11;
    rb.y = b00.y*w00 + b01.y*w01 + b10.y*w10 + b11.y*w11;
    rb.z = b00.z*w00 + b01.z*w01 + b10.z*w10 + b11.z*w11;
    rb.w = b00.w*w00 + b01.w*w01 + b10.w*w10 + b11.w*w11;

    float4* o4 = (float4*)out + gw * C4N;
    __stcs(o4 + cA, ra);
    __stcs(o4 + cB, rb);
}

extern "C" void kernel_launch(void* const* d_in, const int* in_sizes, int n_in,
                              void* d_out, int out_size) {
    const float* boxes = (const float*)d_in[0];
    const float* meta  = (const float*)d_in[1];
    const float* p2    = (const float*)d_in[2];
    const float* p3    = (const float*)d_in[3];
    const float* p4    = (const float*)d_in[4];
    const float* p5    = (const float*)d_in[5];
    float* out = (float*)d_out;

    int B = in_sizes[1] / 93;              // image_meta [B,93]
    if (B <= 0) B = 2;
    int N = in_sizes[0] / (4 * B);         // boxes [B,N,4]
    int M = B * N;
    int totalWarps = M * 49;               // one warp per (roi, py, px)

    int threads = 256;                      // 8 warps per block
    int warpsPerBlock = threads / 32;
    int blocks = (totalWarps + warpsPerBlock - 1) / warpsPerBlock;
    roi_align_warp_kernel<<<blocks, threads>>>(boxes, meta, p2, p3, p4, p5, out,
                                               totalWarps, N);
}